// round 8
// baseline (speedup 1.0000x reference)
#include <cuda_runtime.h>
#include <cuda_bf16.h>

#define NN    64
#define CC    128
#define HWP   3136
#define MTOT  200704
#define EPSI  1e-5f
#define TITER 10
#define NSB   128
#define GBLK  448            // 64 img x 7 chunks
#define GCHUNK 448           // px per chunk
#define GTILES 28            // k16 tiles per chunk

// gram smem: [buf 0/1][prec hi/lo][128 rows][48B]
#define PITCHB 48
#define GPREC  (128 * PITCHB)
#define GBUF   (2 * GPREC)

// whit smem layout
#define WPITCH 272
#define XPITCH 144
#define S_WH   0
#define S_WL   (128*WPITCH)
#define S_XH   (2*128*WPITCH)
#define S_XL   (S_XH + 128*XPITCH)
#define S_BIAS (S_XL + 128*XPITCH)
#define WHIT_SMEM (S_BIAS + 128*4)

#define NS_SMEM (2 * CC * CC * 4)   // Sig_s + P_s = 131072

// ---------------- scratch ----------------
__device__ float d_gpart[GBLK * CC * CC];
__device__ float d_cpart[GBLK * CC];
__device__ float d_gram[CC * CC];
__device__ float d_chsum[CC];
__device__ float d_Sig[CC * CC];
__device__ float d_P2[2][CC * CC];
__device__ __nv_bfloat16 d_wmh[CC * CC];
__device__ __nv_bfloat16 d_wml[CC * CC];
__device__ float d_bias2[CC];
__device__ float d_trace;
__device__ unsigned g_bar;

// ---------------- helpers ----------------
__device__ __forceinline__ unsigned smem_u32(const void* p) {
    unsigned r; asm("{ .reg .u64 t; cvta.to.shared.u64 t, %1; cvt.u32.u64 %0, t; }" : "=r"(r) : "l"(p)); return r;
}
__device__ __forceinline__ void ldsm_x4(unsigned &r0, unsigned &r1, unsigned &r2, unsigned &r3, unsigned a) {
    asm volatile("ldmatrix.sync.aligned.m8n8.x4.shared.b16 {%0,%1,%2,%3}, [%4];"
                 : "=r"(r0), "=r"(r1), "=r"(r2), "=r"(r3) : "r"(a));
}
__device__ __forceinline__ void ldsm_x2t(unsigned &r0, unsigned &r1, unsigned a) {
    asm volatile("ldmatrix.sync.aligned.m8n8.x2.trans.shared.b16 {%0,%1}, [%2];"
                 : "=r"(r0), "=r"(r1) : "r"(a));
}
__device__ __forceinline__ void mma_bf16(float* d, unsigned a0, unsigned a1, unsigned a2, unsigned a3,
                                         unsigned b0, unsigned b1) {
    asm volatile("mma.sync.aligned.m16n8k16.row.col.f32.bf16.bf16.f32 "
                 "{%0,%1,%2,%3}, {%4,%5,%6,%7}, {%8,%9}, {%0,%1,%2,%3};"
                 : "+f"(d[0]), "+f"(d[1]), "+f"(d[2]), "+f"(d[3])
                 : "r"(a0), "r"(a1), "r"(a2), "r"(a3), "r"(b0), "r"(b1));
}
__device__ __forceinline__ unsigned pkbf(float a, float b) {
    __nv_bfloat162 t(__float2bfloat16(a), __float2bfloat16(b));
    return *(unsigned*)&t;
}

// ---------------- kernel 0 ----------------
__global__ void zero_kernel() {
    if (threadIdx.x == 0) { d_trace = 0.f; g_bar = 0u; }
}

// ---------------- kernel 1: Gram via mma.sync bf16 split (448 blocks) ----------------
__global__ void __launch_bounds__(256) gram_kernel(const float* __restrict__ X) {
    __shared__ __align__(16) char sm[2 * GBUF];
    __shared__ float chs[CC];
    const int tid = threadIdx.x, wid = tid >> 5, lane = tid & 31;
    const unsigned smb = smem_u32(sm);
    const int n = blockIdx.x / 7;
    const int pbase = (blockIdx.x % 7) * GCHUNK;
    const float* Xn = X + (size_t)n * (CC * HWP) + pbase;

    const int r = tid >> 1, q = tid & 1;
    const float* gsrc = Xn + (size_t)r * HWP + q * 8;
    if (tid < CC) chs[tid] = 0.f;

    float acc[16][4];
#pragma unroll
    for (int j = 0; j < 16; ++j)
#pragma unroll
        for (int z = 0; z < 4; ++z) acc[j][z] = 0.f;
    float cs = 0.f;

    const unsigned a_off = (unsigned)((wid * 16 + (lane & 15)) * PITCHB + (lane >> 4) * 16);
    const unsigned b_row = (unsigned)((lane >> 4) * 8 + (lane & 7));
    const unsigned b_koff = (unsigned)(((lane >> 3) & 1) * 16);
    const unsigned st_off = (unsigned)(r * PITCHB + q * 16);

    float4 pv0 = *(const float4*)(gsrc);
    float4 pv1 = *(const float4*)(gsrc + 4);

    for (int t = 0; t < GTILES; ++t) {
        char* base = sm + (t & 1) * GBUF;
        {
            unsigned h0 = pkbf(pv0.x, pv0.y), h1 = pkbf(pv0.z, pv0.w);
            unsigned h2 = pkbf(pv1.x, pv1.y), h3 = pkbf(pv1.z, pv1.w);
            float hx, hy, hz, hw;
            __nv_bfloat162 t0 = *(__nv_bfloat162*)&h0; hx = __bfloat162float(t0.x); hy = __bfloat162float(t0.y);
            __nv_bfloat162 t1 = *(__nv_bfloat162*)&h1; hz = __bfloat162float(t1.x); hw = __bfloat162float(t1.y);
            unsigned l0 = pkbf(pv0.x - hx, pv0.y - hy), l1 = pkbf(pv0.z - hz, pv0.w - hw);
            __nv_bfloat162 t2 = *(__nv_bfloat162*)&h2; hx = __bfloat162float(t2.x); hy = __bfloat162float(t2.y);
            __nv_bfloat162 t3 = *(__nv_bfloat162*)&h3; hz = __bfloat162float(t3.x); hw = __bfloat162float(t3.y);
            unsigned l2 = pkbf(pv1.x - hx, pv1.y - hy), l3 = pkbf(pv1.z - hz, pv1.w - hw);
            *(uint4*)(base + st_off)         = make_uint4(h0, h1, h2, h3);
            *(uint4*)(base + GPREC + st_off) = make_uint4(l0, l1, l2, l3);
            cs += ((pv0.x + pv0.y) + (pv0.z + pv0.w)) + ((pv1.x + pv1.y) + (pv1.z + pv1.w));
        }
        __syncthreads();
        if (t < GTILES - 1) {
            pv0 = *(const float4*)(gsrc + (t + 1) * 16);
            pv1 = *(const float4*)(gsrc + (t + 1) * 16 + 4);
        }
        const unsigned tb = smb + (unsigned)((t & 1) * GBUF);
        unsigned ah0, ah1, ah2, ah3, al0, al1, al2, al3;
        ldsm_x4(ah0, ah1, ah2, ah3, tb + a_off);
        ldsm_x4(al0, al1, al2, al3, tb + GPREC + a_off);
#pragma unroll
        for (int p = 0; p < 8; ++p) {
            const unsigned ba = tb + (unsigned)((16 * p + b_row) * PITCHB) + b_koff;
            unsigned bh0, bh1, bh2, bh3, bl0, bl1, bl2, bl3;
            ldsm_x4(bh0, bh1, bh2, bh3, ba);
            ldsm_x4(bl0, bl1, bl2, bl3, ba + GPREC);
            mma_bf16(acc[2*p],   ah0, ah1, ah2, ah3, bh0, bh1);
            mma_bf16(acc[2*p+1], ah0, ah1, ah2, ah3, bh2, bh3);
            mma_bf16(acc[2*p],   ah0, ah1, ah2, ah3, bl0, bl1);
            mma_bf16(acc[2*p+1], ah0, ah1, ah2, ah3, bl2, bl3);
            mma_bf16(acc[2*p],   al0, al1, al2, al3, bh0, bh1);
            mma_bf16(acc[2*p+1], al0, al1, al2, al3, bh2, bh3);
        }
    }

    __syncthreads();
    atomicAdd(&chs[r], cs);
    __syncthreads();
    if (tid < CC) d_cpart[blockIdx.x * CC + tid] = chs[tid];

    float* gp = d_gpart + (size_t)blockIdx.x * (CC * CC);
    const int row0 = wid * 16 + (lane >> 2);
#pragma unroll
    for (int j = 0; j < 16; ++j) {
        const int col = j * 8 + (lane & 3) * 2;
        *(float2*)(gp + row0 * CC + col)       = make_float2(acc[j][0], acc[j][1]);
        *(float2*)(gp + (row0 + 8) * CC + col) = make_float2(acc[j][2], acc[j][3]);
    }
}

// ---------------- kernel 2: reduce ----------------
__global__ void reduce_kernel() {
    const int bid = blockIdx.x, tid = threadIdx.x;
    if (bid < 64) {
        const int i = bid * 256 + tid;
        float s = 0.f;
#pragma unroll 8
        for (int b = 0; b < GBLK; b++) s += d_gpart[(size_t)b * (CC * CC) + i];
        d_gram[i] = s;
    } else if (tid < CC) {
        float s = 0.f;
#pragma unroll 8
        for (int b = 0; b < GBLK; b++) s += d_cpart[b * CC + tid];
        d_chsum[tid] = s;
    }
}

// ---------------- kernel 3: Newton-Schulz, smem-staged @128x128 ----------------
__device__ __forceinline__ void gsync(unsigned &tgt) {
    __threadfence();
    __syncthreads();
    tgt += NSB;
    if (threadIdx.x == 0) {
        atomicAdd(&g_bar, 1u);
        while (*(volatile unsigned*)&g_bar < tgt) {}
    }
    __syncthreads();
}
__device__ __forceinline__ float dots(const float* __restrict__ v,
                                      const float* __restrict__ M, int j) {
    float a0 = 0.f, a1 = 0.f, a2 = 0.f, a3 = 0.f;
#pragma unroll
    for (int k = 0; k < CC; k += 4) {
        float4 pv = *(const float4*)(v + k);
        a0 = fmaf(pv.x, M[(k + 0) * CC + j], a0);
        a1 = fmaf(pv.y, M[(k + 1) * CC + j], a1);
        a2 = fmaf(pv.z, M[(k + 2) * CC + j], a2);
        a3 = fmaf(pv.w, M[(k + 3) * CC + j], a3);
    }
    return (a0 + a1) + (a2 + a3);
}
__global__ void __launch_bounds__(128, 1) ns_kernel(const float* __restrict__ beta) {
    extern __shared__ float dsm[];
    float* Sig_s = dsm;             // 16384
    float* P_s   = dsm + CC * CC;   // 16384
    __shared__ float mean_s[CC], pr_s[CC], t1_s[CC], t2_s[CC];
    __shared__ float rtr_s;
    const int r = blockIdx.x, j = threadIdx.x;

    mean_s[j] = d_chsum[j] * (1.f / (float)MTOT);
    __syncthreads();
    float sig = d_gram[r*CC + j] * (1.f / (float)MTOT) - mean_s[r] * mean_s[j]
                + ((j == r) ? EPSI : 0.f);
    __stcg(&d_Sig[r*CC + j], sig);
    __stcg(&d_P2[0][r*CC + j], (j == r) ? 1.f : 0.f);
    if (j == r) atomicAdd(&d_trace, sig);

    unsigned tgt = 0;
    gsync(tgt);
    if (j == 0) rtr_s = 1.f / *(volatile float*)&d_trace;
    {   // stage Sigma once
        const float4* Sg = (const float4*)d_Sig;
        float4* Ss = (float4*)Sig_s;
#pragma unroll 8
        for (int i = j; i < CC * CC / 4; i += CC) Ss[i] = __ldcg(Sg + i);
    }
    __syncthreads();
    const float rtr = rtr_s;

    int cur = 0;
    for (int it = 0; it < TITER; ++it) {
        {   // stage current P
            const float4* Pg = (const float4*)d_P2[cur];
            float4* Ps = (float4*)P_s;
#pragma unroll 8
            for (int i = j; i < CC * CC / 4; i += CC) Ps[i] = __ldcg(Pg + i);
        }
        __syncthreads();
        float prj = P_s[r * CC + j];
        pr_s[j] = prj;
        __syncthreads();
        t1_s[j] = dots(pr_s, P_s, j);
        __syncthreads();
        t2_s[j] = dots(t1_s, P_s, j);
        __syncthreads();
        float u = dots(t2_s, Sig_s, j);
        __stcg(&d_P2[1 - cur][r * CC + j], 1.5f * prj - 0.5f * rtr * u);
        gsync(tgt);
        cur ^= 1;
    }

    float w = __ldcg(&d_P2[cur][r * CC + j]) * sqrtf(rtr);
    __nv_bfloat16 wh = __float2bfloat16(w);
    float whf = __bfloat162float(wh);
    __nv_bfloat16 wl = __float2bfloat16(w - whf);
    d_wmh[r * CC + j] = wh;
    d_wml[r * CC + j] = wl;
    float wq = whf + __bfloat162float(wl);
    t1_s[j] = wq * mean_s[j];
    __syncthreads();
    for (int s = 64; s > 0; s >>= 1) {
        if (j < s) t1_s[j] += t1_s[j + s];
        __syncthreads();
    }
    if (j == 0) d_bias2[r] = beta[r] - t1_s[0];
}

// ---------------- kernel 4: whitening, 784 CTAs x 4 p-tiles ----------------
__global__ void __launch_bounds__(256) whit_kernel(const float* __restrict__ X,
                                                   float* __restrict__ Y) {
    extern __shared__ char sm[];
    const int tid = threadIdx.x, wid = tid >> 5, lane = tid & 31;
    const unsigned smb = smem_u32(sm);

    {   // stage wm hi/lo once
        const unsigned* wh = (const unsigned*)d_wmh;
        const unsigned* wl = (const unsigned*)d_wml;
#pragma unroll 8
        for (int i = tid; i < 8192; i += 256) {
            int c = i >> 6, dp = i & 63;
            unsigned off = (unsigned)(c * WPITCH + dp * 4);
            *(unsigned*)(sm + S_WH + off) = wh[i];
            *(unsigned*)(sm + S_WL + off) = wl[i];
        }
    }
    if (tid < 128) ((float*)(sm + S_BIAS))[tid] = d_bias2[tid];

    const unsigned arow = (unsigned)(wid * 16 + (lane & 15));
    const unsigned acol = (unsigned)((lane >> 4) * 16);
    const unsigned brln = (unsigned)(lane & 15);
    const int cr = tid >> 2, cq = tid & 3;

    for (int t = 0; t < 4; ++t) {
        const int g = blockIdx.x * 4 + t;
        const int n = g / 49, p0 = (g % 49) * 64;
        if (t) __syncthreads();   // all warps done reading smem X of prev tile
        {   // convert X tile
#pragma unroll
            for (int h = 0; h < 2; ++h) {
                const int row = cr + h * 64;
                const float* xp = X + ((size_t)n * CC + row) * HWP + p0 + cq * 16;
                unsigned hi[8], lo[8];
#pragma unroll
                for (int i = 0; i < 4; ++i) {
                    float4 v = *(const float4*)(xp + 4 * i);
                    __nv_bfloat16 hx = __float2bfloat16(v.x), hy = __float2bfloat16(v.y);
                    __nv_bfloat16 hz = __float2bfloat16(v.z), hw = __float2bfloat16(v.w);
                    __nv_bfloat162 hp0(hx, hy), hp1(hz, hw);
                    hi[2*i]   = *(unsigned*)&hp0;
                    hi[2*i+1] = *(unsigned*)&hp1;
                    lo[2*i]   = pkbf(v.x - __bfloat162float(hx), v.y - __bfloat162float(hy));
                    lo[2*i+1] = pkbf(v.z - __bfloat162float(hz), v.w - __bfloat162float(hw));
                }
                const unsigned off = (unsigned)(row * XPITCH + cq * 32);
                *(uint4*)(sm + S_XH + off)      = make_uint4(hi[0], hi[1], hi[2], hi[3]);
                *(uint4*)(sm + S_XH + off + 16) = make_uint4(hi[4], hi[5], hi[6], hi[7]);
                *(uint4*)(sm + S_XL + off)      = make_uint4(lo[0], lo[1], lo[2], lo[3]);
                *(uint4*)(sm + S_XL + off + 16) = make_uint4(lo[4], lo[5], lo[6], lo[7]);
            }
        }
        __syncthreads();

        float acc[8][4];
#pragma unroll
        for (int jj = 0; jj < 8; ++jj)
#pragma unroll
            for (int z = 0; z < 4; ++z) acc[jj][z] = 0.f;

#pragma unroll
        for (int kt = 0; kt < 8; ++kt) {
            const int k0 = kt * 16;
            unsigned aaddr = smb + S_WH + arow * WPITCH + (unsigned)(k0 * 2) + acol;
            unsigned ah0, ah1, ah2, ah3, al0, al1, al2, al3;
            ldsm_x4(ah0, ah1, ah2, ah3, aaddr);
            ldsm_x4(al0, al1, al2, al3, aaddr + (S_WL - S_WH));
            const unsigned bbase = smb + S_XH + (unsigned)((k0 + brln) * XPITCH);
#pragma unroll
            for (int jj = 0; jj < 8; ++jj) {
                unsigned bh0, bh1, bl0, bl1;
                ldsm_x2t(bh0, bh1, bbase + jj * 16);
                ldsm_x2t(bl0, bl1, bbase + jj * 16 + (S_XL - S_XH));
                mma_bf16(acc[jj], ah0, ah1, ah2, ah3, bh0, bh1);
                mma_bf16(acc[jj], ah0, ah1, ah2, ah3, bl0, bl1);
                mma_bf16(acc[jj], al0, al1, al2, al3, bh0, bh1);
            }
        }

        const int row0 = wid * 16 + (lane >> 2);
        const float b0 = ((const float*)(sm + S_BIAS))[row0];
        const float b1 = ((const float*)(sm + S_BIAS))[row0 + 8];
        float* y0 = Y + ((size_t)n * CC + row0) * HWP + p0 + (lane & 3) * 2;
#pragma unroll
        for (int jj = 0; jj < 8; ++jj) {
            *(float2*)(y0 + 8 * jj)           = make_float2(acc[jj][0] + b0, acc[jj][1] + b0);
            *(float2*)(y0 + 8 * jj + 8 * HWP) = make_float2(acc[jj][2] + b1, acc[jj][3] + b1);
        }
    }
}

// ---------------- launch ----------------
extern "C" void kernel_launch(void* const* d_in, const int* in_sizes, int n_in,
                              void* d_out, int out_size) {
    const float* X = (const float*)d_in[0];
    const float* beta = (const float*)d_in[1];
    float* Y = (float*)d_out;
    cudaFuncSetAttribute(ns_kernel,   cudaFuncAttributeMaxDynamicSharedMemorySize, NS_SMEM);
    cudaFuncSetAttribute(whit_kernel, cudaFuncAttributeMaxDynamicSharedMemorySize, WHIT_SMEM);
    zero_kernel<<<1, 32>>>();
    gram_kernel<<<GBLK, 256>>>(X);
    reduce_kernel<<<65, 256>>>();
    ns_kernel<<<NSB, 128, NS_SMEM>>>(beta);
    whit_kernel<<<784, 256, WHIT_SMEM>>>(X, Y);
}

// round 9
// speedup vs baseline: 1.0882x; 1.0882x over previous
#include <cuda_runtime.h>
#include <cuda_bf16.h>

#define NN    64
#define CC    128
#define HWP   3136
#define MTOT  200704
#define EPSI  1e-5f
#define TITER 10
#define NSB   128
#define GCHUNK 784
#define GBLK  256

// gram smem: [buf 0/1][prec hi/lo][128 rows][48B]
#define PITCHB 48
#define GPREC  (128 * PITCHB)
#define GBUF   (2 * GPREC)

// whit smem layout (bytes, dynamic)
#define WPITCH 272
#define XPITCH 144
#define S_WH   0
#define S_WL   (128*WPITCH)
#define S_XH   (2*128*WPITCH)
#define S_XL   (S_XH + 128*XPITCH)
#define S_BIAS (S_XL + 128*XPITCH)
#define WHIT_SMEM (S_BIAS + 128*4)

// ---------------- scratch ----------------
__device__ float d_gpart[GBLK * CC * CC];
__device__ float d_cpart[GBLK * CC];
__device__ float d_gram[CC * CC];
__device__ float d_chsum[CC];
__device__ float d_Sig[CC * CC];
__device__ float d_P2[2][CC * CC];
__device__ __nv_bfloat16 d_wmh[CC * CC];
__device__ __nv_bfloat16 d_wml[CC * CC];
__device__ float d_bias2[CC];
__device__ float d_trace;
__device__ unsigned g_bar;

// ---------------- helpers ----------------
__device__ __forceinline__ unsigned smem_u32(const void* p) {
    unsigned r; asm("{ .reg .u64 t; cvta.to.shared.u64 t, %1; cvt.u32.u64 %0, t; }" : "=r"(r) : "l"(p)); return r;
}
__device__ __forceinline__ void ldsm_x4(unsigned &r0, unsigned &r1, unsigned &r2, unsigned &r3, unsigned a) {
    asm volatile("ldmatrix.sync.aligned.m8n8.x4.shared.b16 {%0,%1,%2,%3}, [%4];"
                 : "=r"(r0), "=r"(r1), "=r"(r2), "=r"(r3) : "r"(a));
}
__device__ __forceinline__ void ldsm_x2t(unsigned &r0, unsigned &r1, unsigned a) {
    asm volatile("ldmatrix.sync.aligned.m8n8.x2.trans.shared.b16 {%0,%1}, [%2];"
                 : "=r"(r0), "=r"(r1) : "r"(a));
}
__device__ __forceinline__ void mma_bf16(float* d, unsigned a0, unsigned a1, unsigned a2, unsigned a3,
                                         unsigned b0, unsigned b1) {
    asm volatile("mma.sync.aligned.m16n8k16.row.col.f32.bf16.bf16.f32 "
                 "{%0,%1,%2,%3}, {%4,%5,%6,%7}, {%8,%9}, {%0,%1,%2,%3};"
                 : "+f"(d[0]), "+f"(d[1]), "+f"(d[2]), "+f"(d[3])
                 : "r"(a0), "r"(a1), "r"(a2), "r"(a3), "r"(b0), "r"(b1));
}
__device__ __forceinline__ unsigned pkbf(float a, float b) {
    __nv_bfloat162 t(__float2bfloat16(a), __float2bfloat16(b));
    return *(unsigned*)&t;
}

// ---------------- kernel 0 ----------------
__global__ void zero_kernel() {
    if (threadIdx.x == 0) { d_trace = 0.f; g_bar = 0u; }
}

// ---------------- kernel 1: Gram via mma.sync bf16 split (R7 measured-good) ----------------
__global__ void __launch_bounds__(256) gram_kernel(const float* __restrict__ X) {
    __shared__ __align__(16) char sm[2 * GBUF];
    __shared__ float chs[CC];
    const int tid = threadIdx.x, wid = tid >> 5, lane = tid & 31;
    const unsigned smb = smem_u32(sm);
    const int n = blockIdx.x >> 2;
    const int pbase = (blockIdx.x & 3) * GCHUNK;
    const float* Xn = X + (size_t)n * (CC * HWP) + pbase;

    const int r = tid >> 1, q = tid & 1;
    const float* gsrc = Xn + (size_t)r * HWP + q * 8;
    if (tid < CC) chs[tid] = 0.f;

    float acc[16][4];
#pragma unroll
    for (int j = 0; j < 16; ++j)
#pragma unroll
        for (int z = 0; z < 4; ++z) acc[j][z] = 0.f;
    float cs = 0.f;

    const unsigned a_off = (unsigned)((wid * 16 + (lane & 15)) * PITCHB + (lane >> 4) * 16);
    const unsigned b_row = (unsigned)((lane >> 4) * 8 + (lane & 7));
    const unsigned b_koff = (unsigned)(((lane >> 3) & 1) * 16);
    const unsigned st_off = (unsigned)(r * PITCHB + q * 16);

    float4 pv0 = *(const float4*)(gsrc);
    float4 pv1 = *(const float4*)(gsrc + 4);

    for (int t = 0; t < 49; ++t) {
        char* base = sm + (t & 1) * GBUF;
        {
            unsigned h0 = pkbf(pv0.x, pv0.y), h1 = pkbf(pv0.z, pv0.w);
            unsigned h2 = pkbf(pv1.x, pv1.y), h3 = pkbf(pv1.z, pv1.w);
            float hx, hy, hz, hw;
            __nv_bfloat162 t0 = *(__nv_bfloat162*)&h0; hx = __bfloat162float(t0.x); hy = __bfloat162float(t0.y);
            __nv_bfloat162 t1 = *(__nv_bfloat162*)&h1; hz = __bfloat162float(t1.x); hw = __bfloat162float(t1.y);
            unsigned l0 = pkbf(pv0.x - hx, pv0.y - hy), l1 = pkbf(pv0.z - hz, pv0.w - hw);
            __nv_bfloat162 t2 = *(__nv_bfloat162*)&h2; hx = __bfloat162float(t2.x); hy = __bfloat162float(t2.y);
            __nv_bfloat162 t3 = *(__nv_bfloat162*)&h3; hz = __bfloat162float(t3.x); hw = __bfloat162float(t3.y);
            unsigned l2 = pkbf(pv1.x - hx, pv1.y - hy), l3 = pkbf(pv1.z - hz, pv1.w - hw);
            *(uint4*)(base + st_off)         = make_uint4(h0, h1, h2, h3);
            *(uint4*)(base + GPREC + st_off) = make_uint4(l0, l1, l2, l3);
            cs += ((pv0.x + pv0.y) + (pv0.z + pv0.w)) + ((pv1.x + pv1.y) + (pv1.z + pv1.w));
        }
        __syncthreads();
        if (t < 48) {
            pv0 = *(const float4*)(gsrc + (t + 1) * 16);
            pv1 = *(const float4*)(gsrc + (t + 1) * 16 + 4);
        }
        const unsigned tb = smb + (unsigned)((t & 1) * GBUF);
        unsigned ah0, ah1, ah2, ah3, al0, al1, al2, al3;
        ldsm_x4(ah0, ah1, ah2, ah3, tb + a_off);
        ldsm_x4(al0, al1, al2, al3, tb + GPREC + a_off);
#pragma unroll
        for (int p = 0; p < 8; ++p) {
            const unsigned ba = tb + (unsigned)((16 * p + b_row) * PITCHB) + b_koff;
            unsigned bh0, bh1, bh2, bh3, bl0, bl1, bl2, bl3;
            ldsm_x4(bh0, bh1, bh2, bh3, ba);
            ldsm_x4(bl0, bl1, bl2, bl3, ba + GPREC);
            mma_bf16(acc[2*p],   ah0, ah1, ah2, ah3, bh0, bh1);
            mma_bf16(acc[2*p+1], ah0, ah1, ah2, ah3, bh2, bh3);
            mma_bf16(acc[2*p],   ah0, ah1, ah2, ah3, bl0, bl1);
            mma_bf16(acc[2*p+1], ah0, ah1, ah2, ah3, bl2, bl3);
            mma_bf16(acc[2*p],   al0, al1, al2, al3, bh0, bh1);
            mma_bf16(acc[2*p+1], al0, al1, al2, al3, bh2, bh3);
        }
    }

    __syncthreads();
    atomicAdd(&chs[r], cs);
    __syncthreads();
    if (tid < CC) d_cpart[blockIdx.x * CC + tid] = chs[tid];

    float* gp = d_gpart + (size_t)blockIdx.x * (CC * CC);
    const int row0 = wid * 16 + (lane >> 2);
#pragma unroll
    for (int j = 0; j < 16; ++j) {
        const int col = j * 8 + (lane & 3) * 2;
        *(float2*)(gp + row0 * CC + col)       = make_float2(acc[j][0], acc[j][1]);
        *(float2*)(gp + (row0 + 8) * CC + col) = make_float2(acc[j][2], acc[j][3]);
    }
}

// ---------------- kernel 2: reduce ----------------
__global__ void reduce_kernel() {
    const int bid = blockIdx.x, tid = threadIdx.x;
    if (bid < 64) {
        const int i = bid * 256 + tid;
        float s = 0.f;
#pragma unroll 8
        for (int b = 0; b < GBLK; b++) s += d_gpart[(size_t)b * (CC * CC) + i];
        d_gram[i] = s;
    } else if (tid < CC) {
        float s = 0.f;
#pragma unroll 8
        for (int b = 0; b < GBLK; b++) s += d_cpart[b * CC + tid];
        d_chsum[tid] = s;
    }
}

// ---------------- kernel 3: Newton-Schulz, direct-L2, k-split x2 (256 thr) ----------------
__device__ __forceinline__ void gsync(unsigned &tgt) {
    __threadfence();
    __syncthreads();
    tgt += NSB;
    if (threadIdx.x == 0) {
        atomicAdd(&g_bar, 1u);
        while (*(volatile unsigned*)&g_bar < tgt) {}
    }
    __syncthreads();
}
// half-dot: 64 k's starting at v (smem) against M rows (global, L2)
__device__ __forceinline__ float halfdot(const float* __restrict__ v,
                                         const float* __restrict__ M, int j) {
    float a0 = 0.f, a1 = 0.f, a2 = 0.f, a3 = 0.f;
#pragma unroll
    for (int k = 0; k < 64; k += 4) {
        float4 pv = *(const float4*)(v + k);
        a0 = fmaf(pv.x, __ldcg(&M[(k + 0) * CC + j]), a0);
        a1 = fmaf(pv.y, __ldcg(&M[(k + 1) * CC + j]), a1);
        a2 = fmaf(pv.z, __ldcg(&M[(k + 2) * CC + j]), a2);
        a3 = fmaf(pv.w, __ldcg(&M[(k + 3) * CC + j]), a3);
    }
    return (a0 + a1) + (a2 + a3);
}
__global__ void __launch_bounds__(256, 1) ns_kernel(const float* __restrict__ beta) {
    __shared__ float mean_s[CC], pr_s[CC], t1_s[CC], t2_s[CC];
    __shared__ float p1[2][CC], p2[2][CC], pu[2][CC];
    __shared__ float rtr_s;
    const int tid = threadIdx.x;
    const int j = tid & 127, h = tid >> 7;
    const int r = blockIdx.x;

    if (h == 0) mean_s[j] = d_chsum[j] * (1.f / (float)MTOT);
    __syncthreads();
    if (h == 0) {
        float sig = d_gram[r*CC + j] * (1.f / (float)MTOT) - mean_s[r] * mean_s[j]
                    + ((j == r) ? EPSI : 0.f);
        __stcg(&d_Sig[r*CC + j], sig);
        __stcg(&d_P2[0][r*CC + j], (j == r) ? 1.f : 0.f);
        if (j == r) atomicAdd(&d_trace, sig);
    }
    unsigned tgt = 0;
    gsync(tgt);
    if (tid == 0) rtr_s = 1.f / *(volatile float*)&d_trace;
    __syncthreads();
    const float rtr = rtr_s;

    int cur = 0;
    for (int it = 0; it < TITER; ++it) {
        const float* P = d_P2[cur];
        if (h == 0) pr_s[j] = __ldcg(&P[r*CC + j]);
        __syncthreads();
        p1[h][j] = halfdot(pr_s + h*64, P + (size_t)h*64*CC, j);
        __syncthreads();
        if (h == 0) t1_s[j] = p1[0][j] + p1[1][j];
        __syncthreads();
        p2[h][j] = halfdot(t1_s + h*64, P + (size_t)h*64*CC, j);
        __syncthreads();
        if (h == 0) t2_s[j] = p2[0][j] + p2[1][j];
        __syncthreads();
        pu[h][j] = halfdot(t2_s + h*64, d_Sig + (size_t)h*64*CC, j);
        __syncthreads();
        if (h == 0) {
            float u = pu[0][j] + pu[1][j];
            __stcg(&d_P2[1 - cur][r*CC + j], 1.5f * pr_s[j] - 0.5f * rtr * u);
        }
        gsync(tgt);
        cur ^= 1;
    }

    if (h == 0) {
        float w = __ldcg(&d_P2[cur][r*CC + j]) * sqrtf(rtr);
        __nv_bfloat16 wh = __float2bfloat16(w);
        float whf = __bfloat162float(wh);
        __nv_bfloat16 wl = __float2bfloat16(w - whf);
        d_wmh[r*CC + j] = wh;
        d_wml[r*CC + j] = wl;
        float wq = whf + __bfloat162float(wl);
        t1_s[j] = wq * mean_s[j];
    }
    __syncthreads();
    for (int s = 64; s > 0; s >>= 1) {
        if (tid < s) t1_s[tid] += t1_s[tid + s];
        __syncthreads();
    }
    if (tid == 0) d_bias2[r] = beta[r] - t1_s[0];
}

// ---------------- kernel 4: whitening via mma.sync bf16 split (R7 measured-good) ---
__global__ void __launch_bounds__(256) whit_kernel(const float* __restrict__ X,
                                                   float* __restrict__ Y) {
    extern __shared__ char sm[];
    const int tid = threadIdx.x, wid = tid >> 5, lane = tid & 31;
    const unsigned smb = smem_u32(sm);
    const int n = blockIdx.x / 49, pt = blockIdx.x % 49, p0 = pt * 64;

    {
        const unsigned* wh = (const unsigned*)d_wmh;
        const unsigned* wl = (const unsigned*)d_wml;
#pragma unroll 8
        for (int i = tid; i < 8192; i += 256) {
            int c = i >> 6, dp = i & 63;
            unsigned off = (unsigned)(c * WPITCH + dp * 4);
            *(unsigned*)(sm + S_WH + off) = wh[i];
            *(unsigned*)(sm + S_WL + off) = wl[i];
        }
    }
    if (tid < 128) ((float*)(sm + S_BIAS))[tid] = d_bias2[tid];

    {
        const int r = tid >> 2, q = tid & 3;
#pragma unroll
        for (int h = 0; h < 2; ++h) {
            const int row = r + h * 64;
            const float* xp = X + ((size_t)n * CC + row) * HWP + p0 + q * 16;
            unsigned hi[8], lo[8];
#pragma unroll
            for (int i = 0; i < 4; ++i) {
                float4 v = *(const float4*)(xp + 4 * i);
                __nv_bfloat16 hx = __float2bfloat16(v.x), hy = __float2bfloat16(v.y);
                __nv_bfloat16 hz = __float2bfloat16(v.z), hw = __float2bfloat16(v.w);
                __nv_bfloat162 hp0(hx, hy), hp1(hz, hw);
                hi[2*i]   = *(unsigned*)&hp0;
                hi[2*i+1] = *(unsigned*)&hp1;
                lo[2*i]   = pkbf(v.x - __bfloat162float(hx), v.y - __bfloat162float(hy));
                lo[2*i+1] = pkbf(v.z - __bfloat162float(hz), v.w - __bfloat162float(hw));
            }
            const unsigned off = (unsigned)(row * XPITCH + q * 32);
            *(uint4*)(sm + S_XH + off)      = make_uint4(hi[0], hi[1], hi[2], hi[3]);
            *(uint4*)(sm + S_XH + off + 16) = make_uint4(hi[4], hi[5], hi[6], hi[7]);
            *(uint4*)(sm + S_XL + off)      = make_uint4(lo[0], lo[1], lo[2], lo[3]);
            *(uint4*)(sm + S_XL + off + 16) = make_uint4(lo[4], lo[5], lo[6], lo[7]);
        }
    }
    __syncthreads();

    float acc[8][4];
#pragma unroll
    for (int j = 0; j < 8; ++j)
#pragma unroll
        for (int q = 0; q < 4; ++q) acc[j][q] = 0.f;

    const unsigned arow = (unsigned)(wid * 16 + (lane & 15));
    const unsigned acol = (unsigned)((lane >> 4) * 16);
    const unsigned brln = (unsigned)(lane & 15);

#pragma unroll
    for (int kt = 0; kt < 8; ++kt) {
        const int k0 = kt * 16;
        unsigned aaddr = smb + S_WH + arow * WPITCH + (unsigned)(k0 * 2) + acol;
        unsigned ah0, ah1, ah2, ah3, al0, al1, al2, al3;
        ldsm_x4(ah0, ah1, ah2, ah3, aaddr);
        ldsm_x4(al0, al1, al2, al3, aaddr + (S_WL - S_WH));
        const unsigned bbase = smb + S_XH + (unsigned)((k0 + brln) * XPITCH);
#pragma unroll
        for (int j = 0; j < 8; ++j) {
            unsigned bh0, bh1, bl0, bl1;
            ldsm_x2t(bh0, bh1, bbase + j * 16);
            ldsm_x2t(bl0, bl1, bbase + j * 16 + (S_XL - S_XH));
            mma_bf16(acc[j], ah0, ah1, ah2, ah3, bh0, bh1);
            mma_bf16(acc[j], ah0, ah1, ah2, ah3, bl0, bl1);
            mma_bf16(acc[j], al0, al1, al2, al3, bh0, bh1);
        }
    }

    const int row0 = wid * 16 + (lane >> 2);
    const float b0 = ((const float*)(sm + S_BIAS))[row0];
    const float b1 = ((const float*)(sm + S_BIAS))[row0 + 8];
    float* y0 = Y + ((size_t)n * CC + row0) * HWP + p0 + (lane & 3) * 2;
#pragma unroll
    for (int j = 0; j < 8; ++j) {
        *(float2*)(y0 + 8 * j)            = make_float2(acc[j][0] + b0, acc[j][1] + b0);
        *(float2*)(y0 + 8 * j + 8 * HWP)  = make_float2(acc[j][2] + b1, acc[j][3] + b1);
    }
}

// ---------------- launch ----------------
extern "C" void kernel_launch(void* const* d_in, const int* in_sizes, int n_in,
                              void* d_out, int out_size) {
    const float* X = (const float*)d_in[0];
    const float* beta = (const float*)d_in[1];
    float* Y = (float*)d_out;
    cudaFuncSetAttribute(whit_kernel, cudaFuncAttributeMaxDynamicSharedMemorySize, WHIT_SMEM);
    zero_kernel<<<1, 32>>>();
    gram_kernel<<<GBLK, 256>>>(X);
    reduce_kernel<<<65, 256>>>();
    ns_kernel<<<NSB, 256>>>(beta);
    whit_kernel<<<49 * 64, 256, WHIT_SMEM>>>(X, Y);
}

// round 10
// speedup vs baseline: 1.2283x; 1.1288x over previous
#include <cuda_runtime.h>
#include <cuda_bf16.h>

#define NN    64
#define CC    128
#define HWP   3136
#define MTOT  200704
#define EPSI  1e-5f
#define TITER 10
#define NSB   128
#define GCHUNK 784
#define GBLK  256

// gram smem: [buf 0/1][128 rows][48B] (hi only, 1-pass)
#define PITCHB 48
#define GBUF   (128 * PITCHB)       // 6144

// whit smem layout (bytes, dynamic)
#define WPITCH 272
#define XPITCH 144
#define S_WH   0
#define S_WL   (128*WPITCH)
#define S_XH   (2*128*WPITCH)
#define S_XL   (S_XH + 128*XPITCH)
#define S_BIAS (S_XL + 128*XPITCH)
#define WHIT_SMEM (S_BIAS + 128*4)

// ---------------- scratch ----------------
__device__ float d_gpart[GBLK * CC * CC];
__device__ float d_cpart[GBLK * CC];
__device__ float d_gram[CC * CC];
__device__ float d_chsum[CC];
__device__ float d_Sig[CC * CC];
__device__ float d_P2[2][CC * CC];
__device__ __nv_bfloat16 d_wmh[CC * CC];
__device__ __nv_bfloat16 d_wml[CC * CC];
__device__ float d_bias2[CC];
__device__ float d_trace;
__device__ unsigned g_bar;

// ---------------- helpers ----------------
__device__ __forceinline__ unsigned smem_u32(const void* p) {
    unsigned r; asm("{ .reg .u64 t; cvta.to.shared.u64 t, %1; cvt.u32.u64 %0, t; }" : "=r"(r) : "l"(p)); return r;
}
__device__ __forceinline__ void ldsm_x4(unsigned &r0, unsigned &r1, unsigned &r2, unsigned &r3, unsigned a) {
    asm volatile("ldmatrix.sync.aligned.m8n8.x4.shared.b16 {%0,%1,%2,%3}, [%4];"
                 : "=r"(r0), "=r"(r1), "=r"(r2), "=r"(r3) : "r"(a));
}
__device__ __forceinline__ void ldsm_x2t(unsigned &r0, unsigned &r1, unsigned a) {
    asm volatile("ldmatrix.sync.aligned.m8n8.x2.trans.shared.b16 {%0,%1}, [%2];"
                 : "=r"(r0), "=r"(r1) : "r"(a));
}
__device__ __forceinline__ void mma_bf16(float* d, unsigned a0, unsigned a1, unsigned a2, unsigned a3,
                                         unsigned b0, unsigned b1) {
    asm volatile("mma.sync.aligned.m16n8k16.row.col.f32.bf16.bf16.f32 "
                 "{%0,%1,%2,%3}, {%4,%5,%6,%7}, {%8,%9}, {%0,%1,%2,%3};"
                 : "+f"(d[0]), "+f"(d[1]), "+f"(d[2]), "+f"(d[3])
                 : "r"(a0), "r"(a1), "r"(a2), "r"(a3), "r"(b0), "r"(b1));
}
__device__ __forceinline__ unsigned pkbf(float a, float b) {
    __nv_bfloat162 t(__float2bfloat16(a), __float2bfloat16(b));
    return *(unsigned*)&t;
}

// ---------------- kernel 0 ----------------
__global__ void zero_kernel() {
    if (threadIdx.x == 0) { d_trace = 0.f; g_bar = 0u; }
}

// ---------------- kernel 1: Gram via mma.sync, SINGLE-PASS bf16 ----------------
// Error model: bf16 quantization of X is zero-mean independent; Sigma entry error
// ~2e-3/sqrt(m) ~ 5e-6 relative to diagonal -> safe at 1e-3 tolerance.
__global__ void __launch_bounds__(256, 2) gram_kernel(const float* __restrict__ X) {
    __shared__ __align__(16) char sm[2 * GBUF];    // 12288 B
    __shared__ float chs[CC];
    const int tid = threadIdx.x, wid = tid >> 5, lane = tid & 31;
    const unsigned smb = smem_u32(sm);
    const int n = blockIdx.x >> 2;
    const int pbase = (blockIdx.x & 3) * GCHUNK;
    const float* Xn = X + (size_t)n * (CC * HWP) + pbase;

    const int r = tid >> 1, q = tid & 1;
    const float* gsrc = Xn + (size_t)r * HWP + q * 8;
    if (tid < CC) chs[tid] = 0.f;

    float acc[16][4];
#pragma unroll
    for (int j = 0; j < 16; ++j)
#pragma unroll
        for (int z = 0; z < 4; ++z) acc[j][z] = 0.f;
    float cs = 0.f;

    const unsigned a_off = (unsigned)((wid * 16 + (lane & 15)) * PITCHB + (lane >> 4) * 16);
    const unsigned b_row = (unsigned)((lane >> 4) * 8 + (lane & 7));
    const unsigned b_koff = (unsigned)(((lane >> 3) & 1) * 16);
    const unsigned st_off = (unsigned)(r * PITCHB + q * 16);

    float4 pv0 = *(const float4*)(gsrc);
    float4 pv1 = *(const float4*)(gsrc + 4);

    for (int t = 0; t < 49; ++t) {
        char* base = sm + (t & 1) * GBUF;
        {
            unsigned h0 = pkbf(pv0.x, pv0.y), h1 = pkbf(pv0.z, pv0.w);
            unsigned h2 = pkbf(pv1.x, pv1.y), h3 = pkbf(pv1.z, pv1.w);
            *(uint4*)(base + st_off) = make_uint4(h0, h1, h2, h3);
            cs += ((pv0.x + pv0.y) + (pv0.z + pv0.w)) + ((pv1.x + pv1.y) + (pv1.z + pv1.w));
        }
        __syncthreads();
        if (t < 48) {
            pv0 = *(const float4*)(gsrc + (t + 1) * 16);
            pv1 = *(const float4*)(gsrc + (t + 1) * 16 + 4);
        }
        const unsigned tb = smb + (unsigned)((t & 1) * GBUF);
        unsigned ah0, ah1, ah2, ah3;
        ldsm_x4(ah0, ah1, ah2, ah3, tb + a_off);
#pragma unroll
        for (int p = 0; p < 8; ++p) {
            const unsigned ba = tb + (unsigned)((16 * p + b_row) * PITCHB) + b_koff;
            unsigned bh0, bh1, bh2, bh3;
            ldsm_x4(bh0, bh1, bh2, bh3, ba);
            mma_bf16(acc[2*p],   ah0, ah1, ah2, ah3, bh0, bh1);
            mma_bf16(acc[2*p+1], ah0, ah1, ah2, ah3, bh2, bh3);
        }
    }

    __syncthreads();
    atomicAdd(&chs[r], cs);
    __syncthreads();
    if (tid < CC) d_cpart[blockIdx.x * CC + tid] = chs[tid];

    float* gp = d_gpart + (size_t)blockIdx.x * (CC * CC);
    const int row0 = wid * 16 + (lane >> 2);
#pragma unroll
    for (int j = 0; j < 16; ++j) {
        const int col = j * 8 + (lane & 3) * 2;
        *(float2*)(gp + row0 * CC + col)       = make_float2(acc[j][0], acc[j][1]);
        *(float2*)(gp + (row0 + 8) * CC + col) = make_float2(acc[j][2], acc[j][3]);
    }
}

// ---------------- kernel 2: reduce ----------------
__global__ void reduce_kernel() {
    const int bid = blockIdx.x, tid = threadIdx.x;
    if (bid < 64) {
        const int i = bid * 256 + tid;
        float s = 0.f;
#pragma unroll 8
        for (int b = 0; b < GBLK; b++) s += d_gpart[(size_t)b * (CC * CC) + i];
        d_gram[i] = s;
    } else if (tid < CC) {
        float s = 0.f;
#pragma unroll 8
        for (int b = 0; b < GBLK; b++) s += d_cpart[b * CC + tid];
        d_chsum[tid] = s;
    }
}

// ---------------- kernel 3: Newton-Schulz, direct-L2, k-split x2 (measured-best) ----------------
__device__ __forceinline__ void gsync(unsigned &tgt) {
    __threadfence();
    __syncthreads();
    tgt += NSB;
    if (threadIdx.x == 0) {
        atomicAdd(&g_bar, 1u);
        while (*(volatile unsigned*)&g_bar < tgt) {}
    }
    __syncthreads();
}
__device__ __forceinline__ float halfdot(const float* __restrict__ v,
                                         const float* __restrict__ M, int j) {
    float a0 = 0.f, a1 = 0.f, a2 = 0.f, a3 = 0.f;
#pragma unroll
    for (int k = 0; k < 64; k += 4) {
        float4 pv = *(const float4*)(v + k);
        a0 = fmaf(pv.x, __ldcg(&M[(k + 0) * CC + j]), a0);
        a1 = fmaf(pv.y, __ldcg(&M[(k + 1) * CC + j]), a1);
        a2 = fmaf(pv.z, __ldcg(&M[(k + 2) * CC + j]), a2);
        a3 = fmaf(pv.w, __ldcg(&M[(k + 3) * CC + j]), a3);
    }
    return (a0 + a1) + (a2 + a3);
}
__global__ void __launch_bounds__(256, 1) ns_kernel(const float* __restrict__ beta) {
    __shared__ float mean_s[CC], pr_s[CC], t1_s[CC], t2_s[CC];
    __shared__ float p1[2][CC], p2[2][CC], pu[2][CC];
    __shared__ float rtr_s;
    const int tid = threadIdx.x;
    const int j = tid & 127, h = tid >> 7;
    const int r = blockIdx.x;

    if (h == 0) mean_s[j] = d_chsum[j] * (1.f / (float)MTOT);
    __syncthreads();
    if (h == 0) {
        float sig = d_gram[r*CC + j] * (1.f / (float)MTOT) - mean_s[r] * mean_s[j]
                    + ((j == r) ? EPSI : 0.f);
        __stcg(&d_Sig[r*CC + j], sig);
        __stcg(&d_P2[0][r*CC + j], (j == r) ? 1.f : 0.f);
        if (j == r) atomicAdd(&d_trace, sig);
    }
    unsigned tgt = 0;
    gsync(tgt);
    if (tid == 0) rtr_s = 1.f / *(volatile float*)&d_trace;
    __syncthreads();
    const float rtr = rtr_s;

    int cur = 0;
    for (int it = 0; it < TITER; ++it) {
        const float* P = d_P2[cur];
        if (h == 0) pr_s[j] = __ldcg(&P[r*CC + j]);
        __syncthreads();
        p1[h][j] = halfdot(pr_s + h*64, P + (size_t)h*64*CC, j);
        __syncthreads();
        if (h == 0) t1_s[j] = p1[0][j] + p1[1][j];
        __syncthreads();
        p2[h][j] = halfdot(t1_s + h*64, P + (size_t)h*64*CC, j);
        __syncthreads();
        if (h == 0) t2_s[j] = p2[0][j] + p2[1][j];
        __syncthreads();
        pu[h][j] = halfdot(t2_s + h*64, d_Sig + (size_t)h*64*CC, j);
        __syncthreads();
        if (h == 0) {
            float u = pu[0][j] + pu[1][j];
            __stcg(&d_P2[1 - cur][r*CC + j], 1.5f * pr_s[j] - 0.5f * rtr * u);
        }
        gsync(tgt);
        cur ^= 1;
    }

    if (h == 0) {
        float w = __ldcg(&d_P2[cur][r*CC + j]) * sqrtf(rtr);
        __nv_bfloat16 wh = __float2bfloat16(w);
        float whf = __bfloat162float(wh);
        __nv_bfloat16 wl = __float2bfloat16(w - whf);
        d_wmh[r*CC + j] = wh;
        d_wml[r*CC + j] = wl;
        float wq = whf + __bfloat162float(wl);
        t1_s[j] = wq * mean_s[j];
    }
    __syncthreads();
    for (int s = 64; s > 0; s >>= 1) {
        if (tid < s) t1_s[tid] += t1_s[tid + s];
        __syncthreads();
    }
    if (tid == 0) d_bias2[r] = beta[r] - t1_s[0];
}

// ---------------- kernel 4: whitening, 784 CTAs x 4 p-tiles, 3-pass bf16 split ----
__global__ void __launch_bounds__(256) whit_kernel(const float* __restrict__ X,
                                                   float* __restrict__ Y) {
    extern __shared__ char sm[];
    const int tid = threadIdx.x, wid = tid >> 5, lane = tid & 31;
    const unsigned smb = smem_u32(sm);

    {   // stage wm hi/lo once per CTA (amortized over 4 tiles)
        const unsigned* wh = (const unsigned*)d_wmh;
        const unsigned* wl = (const unsigned*)d_wml;
#pragma unroll 8
        for (int i = tid; i < 8192; i += 256) {
            int c = i >> 6, dp = i & 63;
            unsigned off = (unsigned)(c * WPITCH + dp * 4);
            *(unsigned*)(sm + S_WH + off) = wh[i];
            *(unsigned*)(sm + S_WL + off) = wl[i];
        }
    }
    if (tid < 128) ((float*)(sm + S_BIAS))[tid] = d_bias2[tid];

    const unsigned arow = (unsigned)(wid * 16 + (lane & 15));
    const unsigned acol = (unsigned)((lane >> 4) * 16);
    const unsigned brln = (unsigned)(lane & 15);
    const int cr = tid >> 2, cq = tid & 3;

    for (int t = 0; t < 4; ++t) {
        const int g = blockIdx.x * 4 + t;
        const int n = g / 49, p0 = (g % 49) * 64;
        if (t) __syncthreads();
        {   // convert X tile -> bf16 hi/lo
#pragma unroll
            for (int h = 0; h < 2; ++h) {
                const int row = cr + h * 64;
                const float* xp = X + ((size_t)n * CC + row) * HWP + p0 + cq * 16;
                unsigned hi[8], lo[8];
#pragma unroll
                for (int i = 0; i < 4; ++i) {
                    float4 v = *(const float4*)(xp + 4 * i);
                    __nv_bfloat16 hx = __float2bfloat16(v.x), hy = __float2bfloat16(v.y);
                    __nv_bfloat16 hz = __float2bfloat16(v.z), hw = __float2bfloat16(v.w);
                    __nv_bfloat162 hp0(hx, hy), hp1(hz, hw);
                    hi[2*i]   = *(unsigned*)&hp0;
                    hi[2*i+1] = *(unsigned*)&hp1;
                    lo[2*i]   = pkbf(v.x - __bfloat162float(hx), v.y - __bfloat162float(hy));
                    lo[2*i+1] = pkbf(v.z - __bfloat162float(hz), v.w - __bfloat162float(hw));
                }
                const unsigned off = (unsigned)(row * XPITCH + cq * 32);
                *(uint4*)(sm + S_XH + off)      = make_uint4(hi[0], hi[1], hi[2], hi[3]);
                *(uint4*)(sm + S_XH + off + 16) = make_uint4(hi[4], hi[5], hi[6], hi[7]);
                *(uint4*)(sm + S_XL + off)      = make_uint4(lo[0], lo[1], lo[2], lo[3]);
                *(uint4*)(sm + S_XL + off + 16) = make_uint4(lo[4], lo[5], lo[6], lo[7]);
            }
        }
        __syncthreads();

        float acc[8][4];
#pragma unroll
        for (int jj = 0; jj < 8; ++jj)
#pragma unroll
            for (int z = 0; z < 4; ++z) acc[jj][z] = 0.f;

#pragma unroll
        for (int kt = 0; kt < 8; ++kt) {
            const int k0 = kt * 16;
            unsigned aaddr = smb + S_WH + arow * WPITCH + (unsigned)(k0 * 2) + acol;
            unsigned ah0, ah1, ah2, ah3, al0, al1, al2, al3;
            ldsm_x4(ah0, ah1, ah2, ah3, aaddr);
            ldsm_x4(al0, al1, al2, al3, aaddr + (S_WL - S_WH));
            const unsigned bbase = smb + S_XH + (unsigned)((k0 + brln) * XPITCH);
#pragma unroll
            for (int jj = 0; jj < 8; ++jj) {
                unsigned bh0, bh1, bl0, bl1;
                ldsm_x2t(bh0, bh1, bbase + jj * 16);
                ldsm_x2t(bl0, bl1, bbase + jj * 16 + (S_XL - S_XH));
                mma_bf16(acc[jj], ah0, ah1, ah2, ah3, bh0, bh1);
                mma_bf16(acc[jj], ah0, ah1, ah2, ah3, bl0, bl1);
                mma_bf16(acc[jj], al0, al1, al2, al3, bh0, bh1);
            }
        }

        const int row0 = wid * 16 + (lane >> 2);
        const float b0 = ((const float*)(sm + S_BIAS))[row0];
        const float b1 = ((const float*)(sm + S_BIAS))[row0 + 8];
        float* y0 = Y + ((size_t)n * CC + row0) * HWP + p0 + (lane & 3) * 2;
#pragma unroll
        for (int jj = 0; jj < 8; ++jj) {
            *(float2*)(y0 + 8 * jj)           = make_float2(acc[jj][0] + b0, acc[jj][1] + b0);
            *(float2*)(y0 + 8 * jj + 8 * HWP) = make_float2(acc[jj][2] + b1, acc[jj][3] + b1);
        }
    }
}

// ---------------- launch ----------------
extern "C" void kernel_launch(void* const* d_in, const int* in_sizes, int n_in,
                              void* d_out, int out_size) {
    const float* X = (const float*)d_in[0];
    const float* beta = (const float*)d_in[1];
    float* Y = (float*)d_out;
    cudaFuncSetAttribute(whit_kernel, cudaFuncAttributeMaxDynamicSharedMemorySize, WHIT_SMEM);
    zero_kernel<<<1, 32>>>();
    gram_kernel<<<GBLK, 256>>>(X);
    reduce_kernel<<<65, 256>>>();
    ns_kernel<<<NSB, 256>>>(beta);
    whit_kernel<<<784, 256, WHIT_SMEM>>>(X, Y);
}